// round 11
// baseline (speedup 1.0000x reference)
#include <cuda_runtime.h>
#include <cuda_bf16.h>
#include <math.h>

// Problem constants (fixed by the reference)
#define BB   8192
#define DIN  2048
#define HH   1024
#define VV   6
#define TT   6

// ---------------------------------------------------------------------------
// Scratch: static __device__ arrays (no runtime allocation allowed)
// ---------------------------------------------------------------------------
__device__ float g_h [BB * HH];   // GRU hidden state
__device__ float g_zb[BB * HH];   // z pre-activation -> z
__device__ float g_rb[BB * HH];   // r pre-activation -> r*h
__device__ float g_hp[BB * HH];   // h_tilde pre-activation
__device__ float g_Pz[(VV + 1) * HH];   // prev-contribution tables: row v = (W_tok[v]+b_tok)@W*_top,
__device__ float g_Pr[(VV + 1) * HH];   // row VV = start_embed@W*_top
__device__ float g_Ph[(VV + 1) * HH];
__device__ int   g_tok[BB];
__device__ float g_rc [BB];
__device__ float g_nt [BB];

// ---------------------------------------------------------------------------
// Table builder: P*[v][j] = sum_k e_v[k] * W*[k][j],  e_v = W_tok[v]+b_tok (v<V) or start_embed
// W* here are the TOP halves (rows 0..H-1) of the (2H,H) GRU matrices.
// ---------------------------------------------------------------------------
__global__ void build_tables(const float* __restrict__ W_tok,
                             const float* __restrict__ b_tok,
                             const float* __restrict__ start_embed,
                             const float* __restrict__ Wz,
                             const float* __restrict__ Wr,
                             const float* __restrict__ Wh)
{
    int v = blockIdx.y;                       // 0..VV
    int j = blockIdx.x * blockDim.x + threadIdx.x;  // 0..HH-1
    float az = 0.f, ar = 0.f, ah = 0.f;
    for (int k = 0; k < HH; k++) {
        float e = (v < VV) ? (W_tok[v * HH + k] + b_tok[k]) : start_embed[k];
        az += e * Wz[k * HH + j];
        ar += e * Wr[k * HH + j];
        ah += e * Wh[k * HH + j];
    }
    g_Pz[v * HH + j] = az;
    g_Pr[v * HH + j] = ar;
    g_Ph[v * HH + j] = ah;
}

__global__ void init_state()
{
    int b = blockIdx.x * blockDim.x + threadIdx.x;
    if (b < BB) {
        g_tok[b] = VV;      // sentinel: start_embed row of the P tables
        g_rc[b]  = 1.f;
        g_nt[b]  = 0.f;
    }
}

// ---------------------------------------------------------------------------
// SGEMM: C[M,N] = A[M,K] @ B[K,N] (+bias per column). 128x128 tile, BK=8,
// 8x8 per thread, 256 threads, double-buffered shared, fp32 FFMA.
// M=8192, N=1024, K in {1024,2048}; all divisible -> no bounds checks.
// ---------------------------------------------------------------------------
__global__ __launch_bounds__(256, 2)
void sgemm128(const float* __restrict__ A, const float* __restrict__ Bm,
              const float* __restrict__ bias, float* __restrict__ C,
              int K, int lda, int ldb, int ldc)
{
    __shared__ float As[2][8][128];
    __shared__ float Bs[2][8][128];

    const int tid = threadIdx.x;
    const int tx  = tid & 15;         // 0..15 -> 8 cols each
    const int ty  = tid >> 4;         // 0..15 -> 8 rows each
    const int rowBase = blockIdx.y * 128;
    const int colBase = blockIdx.x * 128;

    const int aRow = tid >> 1;        // 0..127
    const int aCol = (tid & 1) * 4;   // 0 or 4
    const int bRow = tid >> 5;        // 0..7
    const int bCol = (tid & 31) * 4;  // 0..124

    const float* Aptr = A + (size_t)(rowBase + aRow) * lda + aCol;
    const float* Bptr = Bm + (size_t)bRow * ldb + colBase + bCol;

    float acc[8][8];
#pragma unroll
    for (int i = 0; i < 8; i++)
#pragma unroll
        for (int j = 0; j < 8; j++) acc[i][j] = 0.f;

    // preload tile 0
    float4 a4 = *(const float4*)Aptr;
    float4 b4 = *(const float4*)Bptr;
    As[0][aCol + 0][aRow] = a4.x;
    As[0][aCol + 1][aRow] = a4.y;
    As[0][aCol + 2][aRow] = a4.z;
    As[0][aCol + 3][aRow] = a4.w;
    *(float4*)&Bs[0][bRow][bCol] = b4;
    __syncthreads();

    const int nTiles = K >> 3;
    int cur = 0;
    for (int kt = 0; kt < nTiles; kt++) {
        if (kt + 1 < nTiles) {
            a4 = *(const float4*)(Aptr + (kt + 1) * 8);
            b4 = *(const float4*)(Bptr + (size_t)(kt + 1) * 8 * ldb);
        }
#pragma unroll
        for (int k = 0; k < 8; k++) {
            float ar[8], br[8];
            *(float4*)&ar[0] = *(const float4*)&As[cur][k][ty * 8];
            *(float4*)&ar[4] = *(const float4*)&As[cur][k][ty * 8 + 4];
            *(float4*)&br[0] = *(const float4*)&Bs[cur][k][tx * 8];
            *(float4*)&br[4] = *(const float4*)&Bs[cur][k][tx * 8 + 4];
#pragma unroll
            for (int i = 0; i < 8; i++)
#pragma unroll
                for (int j = 0; j < 8; j++)
                    acc[i][j] += ar[i] * br[j];
        }
        if (kt + 1 < nTiles) {
            int nxt = cur ^ 1;
            As[nxt][aCol + 0][aRow] = a4.x;
            As[nxt][aCol + 1][aRow] = a4.y;
            As[nxt][aCol + 2][aRow] = a4.z;
            As[nxt][aCol + 3][aRow] = a4.w;
            *(float4*)&Bs[nxt][bRow][bCol] = b4;
            __syncthreads();
            cur = nxt;
        }
    }

#pragma unroll
    for (int i = 0; i < 8; i++) {
        int row = rowBase + ty * 8 + i;
        float* Cp = C + (size_t)row * ldc + colBase + tx * 8;
#pragma unroll
        for (int j = 0; j < 8; j += 4) {
            float4 o;
            float b0 = 0.f, b1 = 0.f, b2 = 0.f, b3 = 0.f;
            if (bias) {
                const float* bp = bias + colBase + tx * 8 + j;
                b0 = bp[0]; b1 = bp[1]; b2 = bp[2]; b3 = bp[3];
            }
            o.x = acc[i][j + 0] + b0;
            o.y = acc[i][j + 1] + b1;
            o.z = acc[i][j + 2] + b2;
            o.w = acc[i][j + 3] + b3;
            *(float4*)(Cp + j) = o;
        }
    }
}

// ---------------------------------------------------------------------------
// Elementwise: z = sigmoid(zpre + Pz[tok] + bz) ; rb = sigmoid(rpre + Pr[tok] + br) * h
// ---------------------------------------------------------------------------
__device__ __forceinline__ float sigmoidf(float x) { return 1.f / (1.f + expf(-x)); }

__global__ void zr_act(const float* __restrict__ bz, const float* __restrict__ br)
{
    int idx = blockIdx.x * blockDim.x + threadIdx.x;   // over BB*HH/4
    int b  = idx >> 8;          // HH/4 = 256
    int j4 = idx & 255;
    int t  = g_tok[b];

    float4 zp = ((const float4*)g_zb)[idx];
    float4 rp = ((const float4*)g_rb)[idx];
    float4 hv = ((const float4*)g_h )[idx];
    float4 pz = ((const float4*)g_Pz)[t * 256 + j4];
    float4 pr = ((const float4*)g_Pr)[t * 256 + j4];
    float4 vz = ((const float4*)bz)[j4];
    float4 vr = ((const float4*)br)[j4];

    float4 z, r;
    z.x = sigmoidf(zp.x + pz.x + vz.x);
    z.y = sigmoidf(zp.y + pz.y + vz.y);
    z.z = sigmoidf(zp.z + pz.z + vz.z);
    z.w = sigmoidf(zp.w + pz.w + vz.w);
    r.x = sigmoidf(rp.x + pr.x + vr.x) * hv.x;
    r.y = sigmoidf(rp.y + pr.y + vr.y) * hv.y;
    r.z = sigmoidf(rp.z + pr.z + vr.z) * hv.z;
    r.w = sigmoidf(rp.w + pr.w + vr.w) * hv.w;

    ((float4*)g_zb)[idx] = z;   // now holds z
    ((float4*)g_rb)[idx] = r;   // now holds r*h
}

// h = (1-z)*h + z*tanh(hpre + Ph[tok] + bh)
__global__ void gru_update(const float* __restrict__ bh)
{
    int idx = blockIdx.x * blockDim.x + threadIdx.x;
    int b  = idx >> 8;
    int j4 = idx & 255;
    int t  = g_tok[b];

    float4 hp = ((const float4*)g_hp)[idx];
    float4 ph = ((const float4*)g_Ph)[t * 256 + j4];
    float4 vb = ((const float4*)bh)[j4];
    float4 z  = ((const float4*)g_zb)[idx];
    float4 h  = ((const float4*)g_h )[idx];

    float4 o;
    o.x = (1.f - z.x) * h.x + z.x * tanhf(hp.x + ph.x + vb.x);
    o.y = (1.f - z.y) * h.y + z.y * tanhf(hp.y + ph.y + vb.y);
    o.z = (1.f - z.z) * h.z + z.z * tanhf(hp.z + ph.z + vb.z);
    o.w = (1.f - z.w) * h.w + z.w * tanhf(hp.w + ph.w + vb.w);
    ((float4*)g_h)[idx] = o;
}

// ---------------------------------------------------------------------------
// Decode: one warp per batch row. logits = h@W_out + b_out; argmax(logits+gumbel);
// writes logits_seq, message slice; updates tok, rc, nt.
// ---------------------------------------------------------------------------
__global__ void decode(const float* __restrict__ W_out,
                       const float* __restrict__ b_out,
                       const float* __restrict__ u_noise,
                       float* __restrict__ out_msg,
                       float* __restrict__ out_logits,
                       int t)
{
    int warp = (blockIdx.x * blockDim.x + threadIdx.x) >> 5;
    int lane = threadIdx.x & 31;
    if (warp >= BB) return;

    const float* hrow = g_h + (size_t)warp * HH;
    float acc[VV];
#pragma unroll
    for (int v = 0; v < VV; v++) acc[v] = 0.f;

    for (int j = lane; j < HH; j += 32) {
        float hv = hrow[j];
        const float* w = W_out + j * VV;
#pragma unroll
        for (int v = 0; v < VV; v++) acc[v] += hv * w[v];
    }
#pragma unroll
    for (int v = 0; v < VV; v++)
#pragma unroll
        for (int off = 16; off; off >>= 1)
            acc[v] += __shfl_xor_sync(0xFFFFFFFFu, acc[v], off);

    if (lane == 0) {
        float rc = g_rc[warp];
        g_nt[warp] += rc;                 // nt uses rc at step start

        const float eps = 1e-10f;
        float best = -1e30f;
        int amax = 0;
        float logits[VV];
#pragma unroll
        for (int v = 0; v < VV; v++) {
            float lg = acc[v] + b_out[v];
            logits[v] = lg;
            float u = u_noise[t * (BB * VV) + warp * VV + v];
            float g = -logf(-logf(u + eps) + eps);
            float a = lg + g;
            if (a > best) { best = a; amax = v; }   // first-max on ties
        }
#pragma unroll
        for (int v = 0; v < VV; v++) {
            out_logits[t * (BB * VV) + warp * VV + v] = logits[v];
            out_msg[warp * (TT * VV) + t * VV + v] = (v == amax) ? rc : 0.f;
        }
        g_tok[warp] = amax;
        if (amax == VV - 1) g_rc[warp] = 0.f;   // STOP symbol
    }
}

__global__ void write_ntokens(float* __restrict__ out_nt)
{
    int b = blockIdx.x * blockDim.x + threadIdx.x;
    if (b < BB) out_nt[b] = g_nt[b];
}

// ---------------------------------------------------------------------------
// kernel_launch
// Inputs (metadata order): x, u_noise, W_enc, b_enc, start_embed, W_tok, b_tok,
//                          Wz, bz, Wr, br, Wh, bh, W_out, b_out
// Output: [message (B, T*V) | logits_seq (T, B, V) | n_tokens (B)] fp32
// ---------------------------------------------------------------------------
extern "C" void kernel_launch(void* const* d_in, const int* in_sizes, int n_in,
                              void* d_out, int out_size)
{
    const float* x          = (const float*)d_in[0];
    const float* u_noise    = (const float*)d_in[1];
    const float* W_enc      = (const float*)d_in[2];
    const float* b_enc      = (const float*)d_in[3];
    const float* start_emb  = (const float*)d_in[4];
    const float* W_tok      = (const float*)d_in[5];
    const float* b_tok      = (const float*)d_in[6];
    const float* Wz         = (const float*)d_in[7];
    const float* bz         = (const float*)d_in[8];
    const float* Wr         = (const float*)d_in[9];
    const float* br         = (const float*)d_in[10];
    const float* Wh         = (const float*)d_in[11];
    const float* bh         = (const float*)d_in[12];
    const float* W_out      = (const float*)d_in[13];
    const float* b_out      = (const float*)d_in[14];

    float* out      = (float*)d_out;
    float* out_msg  = out;                                 // B*T*V
    float* out_log  = out + (size_t)BB * TT * VV;          // T*B*V
    float* out_nt   = out + (size_t)BB * TT * VV + (size_t)TT * BB * VV;

    float *p_h, *p_zb, *p_rb, *p_hp;
    cudaGetSymbolAddress((void**)&p_h,  g_h);
    cudaGetSymbolAddress((void**)&p_zb, g_zb);
    cudaGetSymbolAddress((void**)&p_rb, g_rb);
    cudaGetSymbolAddress((void**)&p_hp, g_hp);

    build_tables<<<dim3(HH / 256, VV + 1), 256>>>(W_tok, b_tok, start_emb, Wz, Wr, Wh);
    init_state<<<(BB + 255) / 256, 256>>>();

    // encoder: h0 = x @ W_enc + b_enc
    sgemm128<<<dim3(HH / 128, BB / 128), 256>>>(x, W_enc, b_enc, p_h,
                                                DIN, DIN, HH, HH);

    const dim3 ggrid(HH / 128, BB / 128);
    const int ew_blocks = (BB * HH / 4) / 256;   // 8192

    for (int t = 0; t < TT; t++) {
        // z/r pre-activations: h @ W*_bottom  (bottom halves of (2H,H) matrices)
        sgemm128<<<ggrid, 256>>>(p_h, Wz + (size_t)HH * HH, nullptr, p_zb,
                                 HH, HH, HH, HH);
        sgemm128<<<ggrid, 256>>>(p_h, Wr + (size_t)HH * HH, nullptr, p_rb,
                                 HH, HH, HH, HH);
        zr_act<<<ew_blocks, 256>>>(bz, br);
        // h_tilde pre-activation: (r*h) @ Wh_bottom
        sgemm128<<<ggrid, 256>>>(p_rb, Wh + (size_t)HH * HH, nullptr, p_hp,
                                 HH, HH, HH, HH);
        gru_update<<<ew_blocks, 256>>>(bh);
        decode<<<(BB * 32) / 256, 256>>>(W_out, b_out, u_noise, out_msg, out_log, t);
    }
    write_ntokens<<<(BB + 255) / 256, 256>>>(out_nt);
}